// round 7
// baseline (speedup 1.0000x reference)
#include <cuda_runtime.h>
#include <cstdint>

#define N_EMBD 1024
#define N_HEAD 16
#define HEAD_DIM 64
#define BATCH 4
#define SEQ 2048
#define C3 (3 * N_EMBD)

// Scratch (no cudaMalloc allowed)
__device__ float g_qkv[BATCH * SEQ * C3];      // ~100.7 MB
__device__ float g_att[BATCH * SEQ * N_EMBD];  // ~33.6 MB

__device__ __forceinline__ uint32_t f2tf32(float x) {
    uint32_t r;
    asm("cvt.rna.tf32.f32 %0, %1;" : "=r"(r) : "f"(x));
    return r;
}

__device__ __forceinline__ void mma_tf32(float c[4], uint32_t a0, uint32_t a1,
                                         uint32_t a2, uint32_t a3,
                                         uint32_t b0, uint32_t b1) {
    asm volatile(
        "mma.sync.aligned.m16n8k8.row.col.f32.tf32.tf32.f32 "
        "{%0,%1,%2,%3}, {%4,%5,%6,%7}, {%8,%9}, {%0,%1,%2,%3};"
        : "+f"(c[0]), "+f"(c[1]), "+f"(c[2]), "+f"(c[3])
        : "r"(a0), "r"(a1), "r"(a2), "r"(a3), "r"(b0), "r"(b1));
}

// ---------------------------------------------------------------------------
// tf32 tensor-core GEMM with bias, double-buffered smem.
// 128x128 block tile, BK=32, 256 threads = 8 warps, warp tile 32x64.
// Dynamic smem: 2 x (As[128][36] + Bs[32][136]) uint32 = 71680 B.
// ---------------------------------------------------------------------------
#define BM 128
#define BN 128
#define BKT 32
#define AS_STRIDE 36
#define BS_STRIDE 136
#define AS_TILE (BM * AS_STRIDE)   // 4608 words
#define BS_TILE (BKT * BS_STRIDE)  // 4352 words
#define GEMM_SMEM ((2 * (AS_TILE + BS_TILE)) * 4)

__global__ __launch_bounds__(256) void gemm_tf32_bias(
    const float* __restrict__ A, const float* __restrict__ B,
    const float* __restrict__ bias, float* __restrict__ C,
    int M, int N, int K)
{
    extern __shared__ uint32_t smg[];
    uint32_t* AsB = smg;                 // [2][128][36]
    uint32_t* BsB = smg + 2 * AS_TILE;   // [2][32][136]

    const int tid = threadIdx.x;
    const int wid = tid >> 5, lane = tid & 31;
    const int wm = wid & 3, wn = wid >> 2;
    const int tg = lane & 3, grp = lane >> 2;
    const int row0 = blockIdx.y * BM, col0 = blockIdx.x * BN;

    const int arow = tid >> 3;
    const int acol = (tid & 7) * 4;
    const int brow = tid >> 5;
    const int bcol = (tid & 31) * 4;

    const float* Ap = A + (long)(row0 + arow) * K + acol;
    const float* Bp = B + (long)brow * N + col0 + bcol;

    float acc[2][8][4];
    #pragma unroll
    for (int mi = 0; mi < 2; mi++)
        #pragma unroll
        for (int ni = 0; ni < 8; ni++)
            #pragma unroll
            for (int e = 0; e < 4; e++) acc[mi][ni][e] = 0.0f;

    float4 ra[4], rb[4];
    const int nt = K / BKT;

    // prefetch + store tile 0 into buffer 0
    #pragma unroll
    for (int p = 0; p < 4; p++) {
        ra[p] = *(const float4*)(Ap + (long)(p * 32) * K);
        rb[p] = *(const float4*)(Bp + (long)(p * 8) * N);
    }
    #pragma unroll
    for (int p = 0; p < 4; p++) {
        uint32_t* as = AsB + (arow + p * 32) * AS_STRIDE + acol;
        as[0] = f2tf32(ra[p].x); as[1] = f2tf32(ra[p].y);
        as[2] = f2tf32(ra[p].z); as[3] = f2tf32(ra[p].w);
        uint32_t* bs = BsB + (brow + p * 8) * BS_STRIDE + bcol;
        bs[0] = f2tf32(rb[p].x); bs[1] = f2tf32(rb[p].y);
        bs[2] = f2tf32(rb[p].z); bs[3] = f2tf32(rb[p].w);
    }
    __syncthreads();

    for (int t = 0; t < nt; t++) {
        const uint32_t* As = AsB + (t & 1) * AS_TILE;
        const uint32_t* Bs = BsB + (t & 1) * BS_TILE;

        if (t + 1 < nt) {
            #pragma unroll
            for (int p = 0; p < 4; p++) {
                ra[p] = *(const float4*)(Ap + (long)(p * 32) * K + (t + 1) * BKT);
                rb[p] = *(const float4*)(Bp + (long)((t + 1) * BKT + p * 8) * N);
            }
        }

        #pragma unroll
        for (int ks = 0; ks < 4; ks++) {
            const int kb = ks * 8;
            uint32_t af[2][4];
            #pragma unroll
            for (int mi = 0; mi < 2; mi++) {
                const int ab = wm * 32 + mi * 16;
                af[mi][0] = As[(ab + grp) * AS_STRIDE + kb + tg];
                af[mi][1] = As[(ab + grp + 8) * AS_STRIDE + kb + tg];
                af[mi][2] = As[(ab + grp) * AS_STRIDE + kb + tg + 4];
                af[mi][3] = As[(ab + grp + 8) * AS_STRIDE + kb + tg + 4];
            }
            #pragma unroll
            for (int ni = 0; ni < 8; ni++) {
                const int nb = wn * 64 + ni * 8 + grp;
                uint32_t b0 = Bs[(kb + tg) * BS_STRIDE + nb];
                uint32_t b1 = Bs[(kb + tg + 4) * BS_STRIDE + nb];
                #pragma unroll
                for (int mi = 0; mi < 2; mi++)
                    mma_tf32(acc[mi][ni], af[mi][0], af[mi][1], af[mi][2],
                             af[mi][3], b0, b1);
            }
        }

        if (t + 1 < nt) {
            uint32_t* Asn = AsB + ((t + 1) & 1) * AS_TILE;
            uint32_t* Bsn = BsB + ((t + 1) & 1) * BS_TILE;
            #pragma unroll
            for (int p = 0; p < 4; p++) {
                uint32_t* as = Asn + (arow + p * 32) * AS_STRIDE + acol;
                as[0] = f2tf32(ra[p].x); as[1] = f2tf32(ra[p].y);
                as[2] = f2tf32(ra[p].z); as[3] = f2tf32(ra[p].w);
                uint32_t* bs = Bsn + (brow + p * 8) * BS_STRIDE + bcol;
                bs[0] = f2tf32(rb[p].x); bs[1] = f2tf32(rb[p].y);
                bs[2] = f2tf32(rb[p].z); bs[3] = f2tf32(rb[p].w);
            }
        }
        __syncthreads();
    }

    #pragma unroll
    for (int mi = 0; mi < 2; mi++) {
        const long r0 = row0 + wm * 32 + mi * 16 + grp;
        const long r1 = r0 + 8;
        #pragma unroll
        for (int ni = 0; ni < 8; ni++) {
            const int c = col0 + wn * 64 + ni * 8 + tg * 2;
            const float bv0 = __ldg(&bias[c]);
            const float bv1 = __ldg(&bias[c + 1]);
            float2 o0 = make_float2(acc[mi][ni][0] + bv0, acc[mi][ni][1] + bv1);
            float2 o1 = make_float2(acc[mi][ni][2] + bv0, acc[mi][ni][3] + bv1);
            *(float2*)&C[r0 * N + c] = o0;
            *(float2*)&C[r1 * N + c] = o1;
        }
    }
}

// ---------------------------------------------------------------------------
// Tensor-core flash attention (causal). One block = (b, h, 64-row q-tile).
// 128 threads = 4 warps, each warp owns 16 q rows (m16 mma slice).
// K hi/lo split precomputed cooperatively at tile load (NOT per-warp in loop).
// S = Q K^T via 3-mma tf32 compensation; O = P V via tf32 mma.
// Strides: Khi/Klo/Ps 68, Vs 72 (bank-conflict-free fragment loads).
// ---------------------------------------------------------------------------
#define QT 64
#define KTILE 64
#define KS_S 68
#define VS_S 72
#define PS_S 68
#define ATT_SMEM ((3 * 64 * KS_S + 64 * VS_S) * 4)  // Khi,Klo,Ps @68 + Vs @72

__global__ __launch_bounds__(128) void flash_attn_tc(
    const float* __restrict__ qkv, float* __restrict__ y)
{
    extern __shared__ float sm[];
    float* Khi = sm;                   // [64][68] tf32 bits
    float* Klo = sm + 64 * KS_S;       // [64][68] tf32 bits
    float* Vs  = sm + 2 * 64 * KS_S;   // [64][72] tf32 bits
    float* Ps  = Vs + 64 * VS_S;       // [64][68] tf32 bits

    const int qt = blockIdx.x, h = blockIdx.y, b = blockIdx.z;
    const int tid = threadIdx.x;
    const int w = tid >> 5, lane = tid & 31;
    const int grp = lane >> 2, tg = lane & 3;
    const int row0 = qt * QT;
    const long base = (long)b * SEQ * C3;
    const int hoff = h * HEAD_DIM;

    // --- Q fragments (scaled by 1/8), hi/lo split, held in registers ---
    uint32_t qhi[8][4], qlo[8][4];
    {
        const float* qA = qkv + base + (long)(row0 + 16 * w + grp) * C3 + hoff;
        const float* qB = qA + 8 * C3;
        #pragma unroll
        for (int ks = 0; ks < 8; ks++) {
            const int k0 = ks * 8 + tg;
            float f;
            f = qA[k0] * 0.125f;
            qhi[ks][0] = f2tf32(f);
            qlo[ks][0] = f2tf32(f - __uint_as_float(qhi[ks][0]));
            f = qB[k0] * 0.125f;
            qhi[ks][1] = f2tf32(f);
            qlo[ks][1] = f2tf32(f - __uint_as_float(qhi[ks][1]));
            f = qA[k0 + 4] * 0.125f;
            qhi[ks][2] = f2tf32(f);
            qlo[ks][2] = f2tf32(f - __uint_as_float(qhi[ks][2]));
            f = qB[k0 + 4] * 0.125f;
            qhi[ks][3] = f2tf32(f);
            qlo[ks][3] = f2tf32(f - __uint_as_float(qhi[ks][3]));
        }
    }

    float oacc[8][4];
    #pragma unroll
    for (int ni = 0; ni < 8; ni++)
        #pragma unroll
        for (int e = 0; e < 4; e++) oacc[ni][e] = 0.0f;
    float mA = -1e30f, mB = -1e30f, lA = 0.0f, lB = 0.0f;

    for (int kt = 0; kt <= qt; kt++) {
        const int kc0 = kt * KTILE;
        __syncthreads();  // prior tile's smem reads done

        // cooperative K hi/lo + V (tf32) tile load
        #pragma unroll
        for (int p = 0; p < 8; p++) {
            const int e = tid + p * 128;
            const int r = e >> 4, c4 = (e & 15) * 4;
            const float* kp = qkv + base + (long)(kc0 + r) * C3 + hoff + N_EMBD + c4;
            const float4 kv = *(const float4*)kp;
            float4 khv, klv;
            khv.x = __uint_as_float(f2tf32(kv.x)); klv.x = __uint_as_float(f2tf32(kv.x - khv.x));
            khv.y = __uint_as_float(f2tf32(kv.y)); klv.y = __uint_as_float(f2tf32(kv.y - khv.y));
            khv.z = __uint_as_float(f2tf32(kv.z)); klv.z = __uint_as_float(f2tf32(kv.z - khv.z));
            khv.w = __uint_as_float(f2tf32(kv.w)); klv.w = __uint_as_float(f2tf32(kv.w - khv.w));
            *(float4*)&Khi[r * KS_S + c4] = khv;
            *(float4*)&Klo[r * KS_S + c4] = klv;
            const float4 vv = *(const float4*)(kp + N_EMBD);
            float4 vt;
            vt.x = __uint_as_float(f2tf32(vv.x));
            vt.y = __uint_as_float(f2tf32(vv.y));
            vt.z = __uint_as_float(f2tf32(vv.z));
            vt.w = __uint_as_float(f2tf32(vv.w));
            *(float4*)&Vs[r * VS_S + c4] = vt;
        }
        __syncthreads();

        // --- S = Q K^T (hi/lo compensated tf32) ---
        float sacc[8][4];
        #pragma unroll
        for (int ni = 0; ni < 8; ni++)
            #pragma unroll
            for (int e = 0; e < 4; e++) sacc[ni][e] = 0.0f;

        #pragma unroll
        for (int ks = 0; ks < 8; ks++) {
            const int kb = ks * 8;
            #pragma unroll
            for (int ni = 0; ni < 8; ni++) {
                const int nb = ni * 8 + grp;
                const uint32_t bh0 = __float_as_uint(Khi[nb * KS_S + kb + tg]);
                const uint32_t bh1 = __float_as_uint(Khi[nb * KS_S + kb + tg + 4]);
                const uint32_t bl0 = __float_as_uint(Klo[nb * KS_S + kb + tg]);
                const uint32_t bl1 = __float_as_uint(Klo[nb * KS_S + kb + tg + 4]);
                mma_tf32(sacc[ni], qhi[ks][0], qhi[ks][1], qhi[ks][2], qhi[ks][3], bh0, bh1);
                mma_tf32(sacc[ni], qhi[ks][0], qhi[ks][1], qhi[ks][2], qhi[ks][3], bl0, bl1);
                mma_tf32(sacc[ni], qlo[ks][0], qlo[ks][1], qlo[ks][2], qlo[ks][3], bh0, bh1);
            }
        }

        // causal mask (diagonal tile only)
        if (kt == qt) {
            const int rA = row0 + 16 * w + grp, rB = rA + 8;
            #pragma unroll
            for (int ni = 0; ni < 8; ni++) {
                const int c0 = kc0 + ni * 8 + 2 * tg;
                if (c0 > rA) sacc[ni][0] = -1e30f;
                if (c0 + 1 > rA) sacc[ni][1] = -1e30f;
                if (c0 > rB) sacc[ni][2] = -1e30f;
                if (c0 + 1 > rB) sacc[ni][3] = -1e30f;
            }
        }

        // --- online softmax (rows grp and grp+8) ---
        float mtA = sacc[0][0], mtB = sacc[0][2];
        #pragma unroll
        for (int ni = 0; ni < 8; ni++) {
            mtA = fmaxf(mtA, fmaxf(sacc[ni][0], sacc[ni][1]));
            mtB = fmaxf(mtB, fmaxf(sacc[ni][2], sacc[ni][3]));
        }
        mtA = fmaxf(mtA, __shfl_xor_sync(0xffffffffu, mtA, 1));
        mtA = fmaxf(mtA, __shfl_xor_sync(0xffffffffu, mtA, 2));
        mtB = fmaxf(mtB, __shfl_xor_sync(0xffffffffu, mtB, 1));
        mtB = fmaxf(mtB, __shfl_xor_sync(0xffffffffu, mtB, 2));

        const float mnA = fmaxf(mA, mtA), mnB = fmaxf(mB, mtB);
        const float cA = __expf(mA - mnA), cB = __expf(mB - mnB);
        mA = mnA; mB = mnB;
        lA *= cA; lB *= cB;
        #pragma unroll
        for (int ni = 0; ni < 8; ni++) {
            oacc[ni][0] *= cA; oacc[ni][1] *= cA;
            oacc[ni][2] *= cB; oacc[ni][3] *= cB;
        }

        float sumA = 0.0f, sumB = 0.0f;
        const int prA = (16 * w + grp) * PS_S;
        const int prB = prA + 8 * PS_S;
        #pragma unroll
        for (int ni = 0; ni < 8; ni++) {
            const float p0 = __expf(sacc[ni][0] - mA);
            const float p1 = __expf(sacc[ni][1] - mA);
            const float p2 = __expf(sacc[ni][2] - mB);
            const float p3 = __expf(sacc[ni][3] - mB);
            sumA += p0 + p1; sumB += p2 + p3;
            const int pc = ni * 8 + 2 * tg;
            uint2 u0 = make_uint2(f2tf32(p0), f2tf32(p1));
            uint2 u1 = make_uint2(f2tf32(p2), f2tf32(p3));
            *(uint2*)&Ps[prA + pc] = u0;
            *(uint2*)&Ps[prB + pc] = u1;
        }
        lA += sumA; lB += sumB;
        __syncwarp();  // P producers/consumers are the same warp

        // --- O += P V (tf32) ---
        #pragma unroll
        for (int ks = 0; ks < 8; ks++) {
            const int kb = ks * 8;
            const uint32_t a0 = __float_as_uint(Ps[prA + kb + tg]);
            const uint32_t a1 = __float_as_uint(Ps[prB + kb + tg]);
            const uint32_t a2 = __float_as_uint(Ps[prA + kb + tg + 4]);
            const uint32_t a3 = __float_as_uint(Ps[prB + kb + tg + 4]);
            #pragma unroll
            for (int ni = 0; ni < 8; ni++) {
                const uint32_t b0 = __float_as_uint(Vs[(kb + tg) * VS_S + ni * 8 + grp]);
                const uint32_t b1 = __float_as_uint(Vs[(kb + tg + 4) * VS_S + ni * 8 + grp]);
                mma_tf32(oacc[ni], a0, a1, a2, a3, b0, b1);
            }
        }
    }

    // --- finalize ---
    lA += __shfl_xor_sync(0xffffffffu, lA, 1);
    lA += __shfl_xor_sync(0xffffffffu, lA, 2);
    lB += __shfl_xor_sync(0xffffffffu, lB, 1);
    lB += __shfl_xor_sync(0xffffffffu, lB, 2);
    const float invA = 1.0f / lA, invB = 1.0f / lB;

    const int rA = row0 + 16 * w + grp, rB = rA + 8;
    float* yA = y + (long)(b * SEQ + rA) * N_EMBD + hoff;
    float* yB = y + (long)(b * SEQ + rB) * N_EMBD + hoff;
    #pragma unroll
    for (int ni = 0; ni < 8; ni++) {
        const int c = ni * 8 + 2 * tg;
        *(float2*)(yA + c) = make_float2(oacc[ni][0] * invA, oacc[ni][1] * invA);
        *(float2*)(yB + c) = make_float2(oacc[ni][2] * invB, oacc[ni][3] * invB);
    }
}

// ---------------------------------------------------------------------------
extern "C" void kernel_launch(void* const* d_in, const int* in_sizes, int n_in,
                              void* d_out, int out_size)
{
    const float* x      = (const float*)d_in[0];
    const float* W_attn = (const float*)d_in[1];
    const float* b_attn = (const float*)d_in[2];
    const float* W_proj = (const float*)d_in[3];
    const float* b_proj = (const float*)d_in[4];
    float* out = (float*)d_out;

    float* qkv = nullptr;
    float* att = nullptr;
    cudaGetSymbolAddress((void**)&qkv, g_qkv);
    cudaGetSymbolAddress((void**)&att, g_att);

    static bool attr_set = false;
    if (!attr_set) {
        cudaFuncSetAttribute(flash_attn_tc,
                             cudaFuncAttributeMaxDynamicSharedMemorySize,
                             ATT_SMEM);
        cudaFuncSetAttribute(gemm_tf32_bias,
                             cudaFuncAttributeMaxDynamicSharedMemorySize,
                             GEMM_SMEM);
        attr_set = true;
    }

    const int M = BATCH * SEQ;  // 8192

    // 1) qkv = x @ W_attn + b_attn   [8192 x 3072]
    gemm_tf32_bias<<<dim3(C3 / BN, M / BM), 256, GEMM_SMEM>>>(
        x, W_attn, b_attn, qkv, M, C3, N_EMBD);

    // 2) causal flash attention (tensor core) -> att [8192 x 1024]
    flash_attn_tc<<<dim3(SEQ / QT, N_HEAD, BATCH), 128, ATT_SMEM>>>(qkv, att);

    // 3) out = att @ W_proj + b_proj  [8192 x 1024]
    gemm_tf32_bias<<<dim3(N_EMBD / BN, M / BM), 256, GEMM_SMEM>>>(
        att, W_proj, b_proj, out, M, N_EMBD, N_EMBD);
}

// round 9
// speedup vs baseline: 1.7570x; 1.7570x over previous
#include <cuda_runtime.h>
#include <cstdint>

#define N_EMBD 1024
#define N_HEAD 16
#define HEAD_DIM 64
#define BATCH 4
#define SEQ 2048
#define C3 (3 * N_EMBD)

// Scratch (no cudaMalloc allowed)
__device__ float g_qkv[BATCH * SEQ * C3];      // ~100.7 MB
__device__ float g_att[BATCH * SEQ * N_EMBD];  // ~33.6 MB

__device__ __forceinline__ uint32_t f2tf32(float x) {
    uint32_t r;
    asm("cvt.rna.tf32.f32 %0, %1;" : "=r"(r) : "f"(x));
    return r;
}

__device__ __forceinline__ void mma_tf32(float c[4], uint32_t a0, uint32_t a1,
                                         uint32_t a2, uint32_t a3,
                                         uint32_t b0, uint32_t b1) {
    asm volatile(
        "mma.sync.aligned.m16n8k8.row.col.f32.tf32.tf32.f32 "
        "{%0,%1,%2,%3}, {%4,%5,%6,%7}, {%8,%9}, {%0,%1,%2,%3};"
        : "+f"(c[0]), "+f"(c[1]), "+f"(c[2]), "+f"(c[3])
        : "r"(a0), "r"(a1), "r"(a2), "r"(a3), "r"(b0), "r"(b1));
}

// ---------------------------------------------------------------------------
// tf32 tensor-core GEMM with bias (exact round-5 version: single-buffered,
// static smem, regs<=124 -> 2 blocks/SM).
// ---------------------------------------------------------------------------
#define BM 128
#define BN 128
#define BKT 32

__global__ __launch_bounds__(256) void gemm_tf32_bias(
    const float* __restrict__ A, const float* __restrict__ B,
    const float* __restrict__ bias, float* __restrict__ C,
    int M, int N, int K)
{
    __shared__ uint32_t As[BM][36];
    __shared__ uint32_t Bs[BKT][136];

    const int tid = threadIdx.x;
    const int wid = tid >> 5, lane = tid & 31;
    const int wm = wid & 3, wn = wid >> 2;
    const int tg = lane & 3, grp = lane >> 2;
    const int row0 = blockIdx.y * BM, col0 = blockIdx.x * BN;

    const int arow = tid >> 3;
    const int acol = (tid & 7) * 4;
    const int brow = tid >> 5;
    const int bcol = (tid & 31) * 4;

    const float* Ap = A + (long)(row0 + arow) * K + acol;
    const float* Bp = B + (long)brow * N + col0 + bcol;

    float acc[2][8][4];
    #pragma unroll
    for (int mi = 0; mi < 2; mi++)
        #pragma unroll
        for (int ni = 0; ni < 8; ni++)
            #pragma unroll
            for (int e = 0; e < 4; e++) acc[mi][ni][e] = 0.0f;

    float4 ra[4], rb[4];
    const int nt = K / BKT;

    #pragma unroll
    for (int p = 0; p < 4; p++) {
        ra[p] = *(const float4*)(Ap + (long)(p * 32) * K);
        rb[p] = *(const float4*)(Bp + (long)(p * 8) * N);
    }

    for (int t = 0; t < nt; t++) {
        #pragma unroll
        for (int p = 0; p < 4; p++) {
            As[arow + p * 32][acol + 0] = f2tf32(ra[p].x);
            As[arow + p * 32][acol + 1] = f2tf32(ra[p].y);
            As[arow + p * 32][acol + 2] = f2tf32(ra[p].z);
            As[arow + p * 32][acol + 3] = f2tf32(ra[p].w);
            Bs[brow + p * 8][bcol + 0] = f2tf32(rb[p].x);
            Bs[brow + p * 8][bcol + 1] = f2tf32(rb[p].y);
            Bs[brow + p * 8][bcol + 2] = f2tf32(rb[p].z);
            Bs[brow + p * 8][bcol + 3] = f2tf32(rb[p].w);
        }
        __syncthreads();

        if (t + 1 < nt) {
            #pragma unroll
            for (int p = 0; p < 4; p++) {
                ra[p] = *(const float4*)(Ap + (long)(p * 32) * K + (t + 1) * BKT);
                rb[p] = *(const float4*)(Bp + (long)((t + 1) * BKT + p * 8) * N);
            }
        }

        #pragma unroll
        for (int ks = 0; ks < 4; ks++) {
            const int kb = ks * 8;
            uint32_t af[2][4];
            #pragma unroll
            for (int mi = 0; mi < 2; mi++) {
                const int ab = wm * 32 + mi * 16;
                af[mi][0] = As[ab + grp][kb + tg];
                af[mi][1] = As[ab + grp + 8][kb + tg];
                af[mi][2] = As[ab + grp][kb + tg + 4];
                af[mi][3] = As[ab + grp + 8][kb + tg + 4];
            }
            #pragma unroll
            for (int ni = 0; ni < 8; ni++) {
                const int nb = wn * 64 + ni * 8 + grp;
                uint32_t b0 = Bs[kb + tg][nb];
                uint32_t b1 = Bs[kb + tg + 4][nb];
                #pragma unroll
                for (int mi = 0; mi < 2; mi++)
                    mma_tf32(acc[mi][ni], af[mi][0], af[mi][1], af[mi][2],
                             af[mi][3], b0, b1);
            }
        }
        __syncthreads();
    }

    #pragma unroll
    for (int mi = 0; mi < 2; mi++) {
        const long r0 = row0 + wm * 32 + mi * 16 + grp;
        const long r1 = r0 + 8;
        #pragma unroll
        for (int ni = 0; ni < 8; ni++) {
            const int c = col0 + wn * 64 + ni * 8 + tg * 2;
            const float bv0 = __ldg(&bias[c]);
            const float bv1 = __ldg(&bias[c + 1]);
            float2 o0 = make_float2(acc[mi][ni][0] + bv0, acc[mi][ni][1] + bv1);
            float2 o1 = make_float2(acc[mi][ni][2] + bv0, acc[mi][ni][3] + bv1);
            *(float2*)&C[r0 * N + c] = o0;
            *(float2*)&C[r1 * N + c] = o1;
        }
    }
}

// ---------------------------------------------------------------------------
// Tensor-core flash attention (causal). One block = (b, h, 64-row q-tile).
// 128 threads = 4 warps, each warp owns 16 q rows (m16 mma slice).
// K hi/lo precomputed cooperatively at tile load (no cvt in S loop).
// P handed to the PV mma via register shuffles (no Ps smem array) -> smem
// stays at 53.2 KB = 4 blocks/SM (round-5 occupancy budget).
// ---------------------------------------------------------------------------
#define QT 64
#define KTILE 64
#define KS_S 68
#define VS_S 72
#define ATT_SMEM ((2 * 64 * KS_S + 64 * VS_S) * 4)  // Khi,Klo @68 + Vs @72

__global__ __launch_bounds__(128) void flash_attn_tc(
    const float* __restrict__ qkv, float* __restrict__ y)
{
    extern __shared__ float sm[];
    float* Khi = sm;                   // [64][68] tf32 bits
    float* Klo = sm + 64 * KS_S;       // [64][68] tf32 bits
    float* Vs  = sm + 2 * 64 * KS_S;   // [64][72] tf32 bits

    const int qt = blockIdx.x, h = blockIdx.y, b = blockIdx.z;
    const int tid = threadIdx.x;
    const int w = tid >> 5, lane = tid & 31;
    const int grp = lane >> 2, tg = lane & 3;
    const int row0 = qt * QT;
    const long base = (long)b * SEQ * C3;
    const int hoff = h * HEAD_DIM;

    // --- Q fragments (scaled by 1/8), hi/lo split, held in registers ---
    uint32_t qhi[8][4], qlo[8][4];
    {
        const float* qA = qkv + base + (long)(row0 + 16 * w + grp) * C3 + hoff;
        const float* qB = qA + 8 * C3;
        #pragma unroll
        for (int ks = 0; ks < 8; ks++) {
            const int k0 = ks * 8 + tg;
            float f;
            f = qA[k0] * 0.125f;
            qhi[ks][0] = f2tf32(f);
            qlo[ks][0] = f2tf32(f - __uint_as_float(qhi[ks][0]));
            f = qB[k0] * 0.125f;
            qhi[ks][1] = f2tf32(f);
            qlo[ks][1] = f2tf32(f - __uint_as_float(qhi[ks][1]));
            f = qA[k0 + 4] * 0.125f;
            qhi[ks][2] = f2tf32(f);
            qlo[ks][2] = f2tf32(f - __uint_as_float(qhi[ks][2]));
            f = qB[k0 + 4] * 0.125f;
            qhi[ks][3] = f2tf32(f);
            qlo[ks][3] = f2tf32(f - __uint_as_float(qhi[ks][3]));
        }
    }

    float oacc[8][4];
    #pragma unroll
    for (int ni = 0; ni < 8; ni++)
        #pragma unroll
        for (int e = 0; e < 4; e++) oacc[ni][e] = 0.0f;
    float mA = -1e30f, mB = -1e30f, lA = 0.0f, lB = 0.0f;

    for (int kt = 0; kt <= qt; kt++) {
        const int kc0 = kt * KTILE;
        __syncthreads();  // prior tile's smem reads done

        // cooperative K hi/lo + V (tf32) tile load
        #pragma unroll
        for (int p = 0; p < 8; p++) {
            const int e = tid + p * 128;
            const int r = e >> 4, c4 = (e & 15) * 4;
            const float* kp = qkv + base + (long)(kc0 + r) * C3 + hoff + N_EMBD + c4;
            const float4 kv = *(const float4*)kp;
            float4 khv, klv;
            khv.x = __uint_as_float(f2tf32(kv.x)); klv.x = __uint_as_float(f2tf32(kv.x - khv.x));
            khv.y = __uint_as_float(f2tf32(kv.y)); klv.y = __uint_as_float(f2tf32(kv.y - khv.y));
            khv.z = __uint_as_float(f2tf32(kv.z)); klv.z = __uint_as_float(f2tf32(kv.z - khv.z));
            khv.w = __uint_as_float(f2tf32(kv.w)); klv.w = __uint_as_float(f2tf32(kv.w - khv.w));
            *(float4*)&Khi[r * KS_S + c4] = khv;
            *(float4*)&Klo[r * KS_S + c4] = klv;
            const float4 vv = *(const float4*)(kp + N_EMBD);
            float4 vt;
            vt.x = __uint_as_float(f2tf32(vv.x));
            vt.y = __uint_as_float(f2tf32(vv.y));
            vt.z = __uint_as_float(f2tf32(vv.z));
            vt.w = __uint_as_float(f2tf32(vv.w));
            *(float4*)&Vs[r * VS_S + c4] = vt;
        }
        __syncthreads();

        // --- S = Q K^T (hi/lo compensated tf32) ---
        float sacc[8][4];
        #pragma unroll
        for (int ni = 0; ni < 8; ni++)
            #pragma unroll
            for (int e = 0; e < 4; e++) sacc[ni][e] = 0.0f;

        #pragma unroll
        for (int ks = 0; ks < 8; ks++) {
            const int kb = ks * 8;
            #pragma unroll
            for (int ni = 0; ni < 8; ni++) {
                const int nb = ni * 8 + grp;
                const uint32_t bh0 = __float_as_uint(Khi[nb * KS_S + kb + tg]);
                const uint32_t bh1 = __float_as_uint(Khi[nb * KS_S + kb + tg + 4]);
                const uint32_t bl0 = __float_as_uint(Klo[nb * KS_S + kb + tg]);
                const uint32_t bl1 = __float_as_uint(Klo[nb * KS_S + kb + tg + 4]);
                mma_tf32(sacc[ni], qhi[ks][0], qhi[ks][1], qhi[ks][2], qhi[ks][3], bh0, bh1);
                mma_tf32(sacc[ni], qhi[ks][0], qhi[ks][1], qhi[ks][2], qhi[ks][3], bl0, bl1);
                mma_tf32(sacc[ni], qlo[ks][0], qlo[ks][1], qlo[ks][2], qlo[ks][3], bh0, bh1);
            }
        }

        // causal mask (diagonal tile only)
        if (kt == qt) {
            const int rA = row0 + 16 * w + grp, rB = rA + 8;
            #pragma unroll
            for (int ni = 0; ni < 8; ni++) {
                const int c0 = kc0 + ni * 8 + 2 * tg;
                if (c0 > rA) sacc[ni][0] = -1e30f;
                if (c0 + 1 > rA) sacc[ni][1] = -1e30f;
                if (c0 > rB) sacc[ni][2] = -1e30f;
                if (c0 + 1 > rB) sacc[ni][3] = -1e30f;
            }
        }

        // --- online softmax (rows grp and grp+8) ---
        float mtA = sacc[0][0], mtB = sacc[0][2];
        #pragma unroll
        for (int ni = 0; ni < 8; ni++) {
            mtA = fmaxf(mtA, fmaxf(sacc[ni][0], sacc[ni][1]));
            mtB = fmaxf(mtB, fmaxf(sacc[ni][2], sacc[ni][3]));
        }
        mtA = fmaxf(mtA, __shfl_xor_sync(0xffffffffu, mtA, 1));
        mtA = fmaxf(mtA, __shfl_xor_sync(0xffffffffu, mtA, 2));
        mtB = fmaxf(mtB, __shfl_xor_sync(0xffffffffu, mtB, 1));
        mtB = fmaxf(mtB, __shfl_xor_sync(0xffffffffu, mtB, 2));

        const float mnA = fmaxf(mA, mtA), mnB = fmaxf(mB, mtB);
        const float cA = __expf(mA - mnA), cB = __expf(mB - mnB);
        mA = mnA; mB = mnB;
        lA *= cA; lB *= cB;
        #pragma unroll
        for (int ni = 0; ni < 8; ni++) {
            oacc[ni][0] *= cA; oacc[ni][1] *= cA;
            oacc[ni][2] *= cB; oacc[ni][3] *= cB;
        }

        // exp -> probabilities in accumulator layout (tf32 bits, registers)
        uint32_t up[8][4];
        float sumA = 0.0f, sumB = 0.0f;
        #pragma unroll
        for (int ni = 0; ni < 8; ni++) {
            const float p0 = __expf(sacc[ni][0] - mA);
            const float p1 = __expf(sacc[ni][1] - mA);
            const float p2 = __expf(sacc[ni][2] - mB);
            const float p3 = __expf(sacc[ni][3] - mB);
            sumA += p0 + p1; sumB += p2 + p3;
            up[ni][0] = f2tf32(p0); up[ni][1] = f2tf32(p1);
            up[ni][2] = f2tf32(p2); up[ni][3] = f2tf32(p3);
        }
        lA += sumA; lB += sumB;

        // --- O += P V: A-fragments of P via intra-warp shuffles ---
        // target lane grp*4+tg needs P(grp, kb+tg): src lane grp*4+(tg>>1),
        // element d[tg&1] (d[2+(tg&1)] for row grp+8); cols tg+4 -> src+2.
        const int src0 = (lane & ~3) | (tg >> 1);
        const int src2 = src0 | 2;
        const bool odd = (tg & 1) != 0;
        #pragma unroll
        for (int ks = 0; ks < 8; ks++) {
            const int kb = ks * 8;
            const uint32_t w00 = __shfl_sync(0xffffffffu, up[ks][0], src0);
            const uint32_t w01 = __shfl_sync(0xffffffffu, up[ks][1], src0);
            const uint32_t w02 = __shfl_sync(0xffffffffu, up[ks][2], src0);
            const uint32_t w03 = __shfl_sync(0xffffffffu, up[ks][3], src0);
            const uint32_t w20 = __shfl_sync(0xffffffffu, up[ks][0], src2);
            const uint32_t w21 = __shfl_sync(0xffffffffu, up[ks][1], src2);
            const uint32_t w22 = __shfl_sync(0xffffffffu, up[ks][2], src2);
            const uint32_t w23 = __shfl_sync(0xffffffffu, up[ks][3], src2);
            const uint32_t a0 = odd ? w01 : w00;
            const uint32_t a1 = odd ? w03 : w02;
            const uint32_t a2 = odd ? w21 : w20;
            const uint32_t a3 = odd ? w23 : w22;
            #pragma unroll
            for (int ni = 0; ni < 8; ni++) {
                const uint32_t b0 = __float_as_uint(Vs[(kb + tg) * VS_S + ni * 8 + grp]);
                const uint32_t b1 = __float_as_uint(Vs[(kb + tg + 4) * VS_S + ni * 8 + grp]);
                mma_tf32(oacc[ni], a0, a1, a2, a3, b0, b1);
            }
        }
    }

    // --- finalize ---
    lA += __shfl_xor_sync(0xffffffffu, lA, 1);
    lA += __shfl_xor_sync(0xffffffffu, lA, 2);
    lB += __shfl_xor_sync(0xffffffffu, lB, 1);
    lB += __shfl_xor_sync(0xffffffffu, lB, 2);
    const float invA = 1.0f / lA, invB = 1.0f / lB;

    const int rA = row0 + 16 * w + grp, rB = rA + 8;
    float* yA = y + (long)(b * SEQ + rA) * N_EMBD + hoff;
    float* yB = y + (long)(b * SEQ + rB) * N_EMBD + hoff;
    #pragma unroll
    for (int ni = 0; ni < 8; ni++) {
        const int c = ni * 8 + 2 * tg;
        *(float2*)(yA + c) = make_float2(oacc[ni][0] * invA, oacc[ni][1] * invA);
        *(float2*)(yB + c) = make_float2(oacc[ni][2] * invB, oacc[ni][3] * invB);
    }
}

// ---------------------------------------------------------------------------
extern "C" void kernel_launch(void* const* d_in, const int* in_sizes, int n_in,
                              void* d_out, int out_size)
{
    const float* x      = (const float*)d_in[0];
    const float* W_attn = (const float*)d_in[1];
    const float* b_attn = (const float*)d_in[2];
    const float* W_proj = (const float*)d_in[3];
    const float* b_proj = (const float*)d_in[4];
    float* out = (float*)d_out;

    float* qkv = nullptr;
    float* att = nullptr;
    cudaGetSymbolAddress((void**)&qkv, g_qkv);
    cudaGetSymbolAddress((void**)&att, g_att);

    static bool attr_set = false;
    if (!attr_set) {
        cudaFuncSetAttribute(flash_attn_tc,
                             cudaFuncAttributeMaxDynamicSharedMemorySize,
                             ATT_SMEM);
        attr_set = true;
    }

    const int M = BATCH * SEQ;  // 8192

    // 1) qkv = x @ W_attn + b_attn   [8192 x 3072]
    gemm_tf32_bias<<<dim3(C3 / BN, M / BM), 256>>>(
        x, W_attn, b_attn, qkv, M, C3, N_EMBD);

    // 2) causal flash attention (tensor core) -> att [8192 x 1024]
    flash_attn_tc<<<dim3(SEQ / QT, N_HEAD, BATCH), 128, ATT_SMEM>>>(qkv, att);

    // 3) out = att @ W_proj + b_proj  [8192 x 1024]
    gemm_tf32_bias<<<dim3(N_EMBD / BN, M / BM), 256>>>(
        att, W_proj, b_proj, out, M, N_EMBD, N_EMBD);
}